// round 9
// baseline (speedup 1.0000x reference)
#include <cuda_runtime.h>

typedef unsigned long long ull;

#define WIDTHK  128
#define DD      8
#define NPTS    65536
#define QPTS    (NPTS/4)      // 16384 threads, 4 points each
#define TVALS   8
#define TSTRIDE 4608          // floats per table: 128 rows * 36 floats
#define NTAB    7             // t0, t1.5, t3, t4.5, t6, t6.5, t7
#define PARTS   4             // hyper blocks per table

// ---------------- packed f32x2 helpers (sm_103a) ----------------
__device__ __forceinline__ ull pk2(float a, float b){ ull r; asm("mov.b64 %0,{%1,%2};":"=l"(r):"f"(a),"f"(b)); return r; }
__device__ __forceinline__ void upk2(ull v, float&a, float&b){ asm("mov.b64 {%0,%1},%2;":"=f"(a),"=f"(b):"l"(v)); }
__device__ __forceinline__ ull ffma2(ull a, ull b, ull c){ ull d; asm("fma.rn.f32x2 %0,%1,%2,%3;":"=l"(d):"l"(a),"l"(b),"l"(c)); return d; }
__device__ __forceinline__ ull fmul2(ull a, ull b){ ull d; asm("mul.rn.f32x2 %0,%1,%2;":"=l"(d):"l"(a),"l"(b)); return d; }
__device__ __forceinline__ ull fadd2(ull a, ull b){ ull d; asm("add.rn.f32x2 %0,%1,%2;":"=l"(d):"l"(a),"l"(b)); return d; }
__device__ __forceinline__ float tanha(float x){ float r; asm("tanh.approx.f32 %0,%1;":"=f"(r):"f"(x)); return r; }

#define NEGONE2 0xBF800000BF800000ULL   // (-1.f, -1.f)

// Hypernet tables. Per-k row (36 floats / 144B):
//  [0:16)  W[k][0..7] each duplicated  (8 x f32x2)
//  [16:32) U'[k][0..7] duplicated, U' = U*sigmoid(G)/128
//  [32:36) B,B,c',c'   where c' = W_k . U'_k
__device__ float g_tables[NTAB * TSTRIDE];

__device__ __forceinline__ float warp_sum(float v){
    #pragma unroll
    for (int o = 16; o > 0; o >>= 1)
        v += __shfl_xor_sync(0xffffffffu, v, o);
    return v;
}

// ---------------- phase 1: hypernetwork (coalesced, warp-per-row) ----------------
__global__ void __launch_bounds__(256)
hyper_kernel(const float* __restrict__ ts,
             const float* __restrict__ w1, const float* __restrict__ b1,
             const float* __restrict__ w2, const float* __restrict__ b2,
             const float* __restrict__ w3, const float* __restrict__ b3)
{
    __shared__ float h1[64], h2s[64];
    __shared__ float Wsh[256], Ush[256];   // this part's 32 k-rows x 8

    int blk  = blockIdx.x;
    int tbi  = blk / PARTS;
    int part = blk % PARTS;

    float t;
    switch (tbi) {
        case 0: t = ts[0]; break;
        case 1: t = 0.5f * (ts[1] + ts[2]); break;
        case 2: t = ts[3]; break;
        case 3: t = 0.5f * (ts[4] + ts[5]); break;
        case 4: t = ts[6]; break;
        case 5: t = 0.5f * (ts[6] + ts[7]); break;
        default: t = ts[7]; break;
    }

    int tid = threadIdx.x;
    int lid = tid & 31, wid = tid >> 5;

    if (tid < 64) h1[tid] = tanhf(w1[tid] * t + b1[tid]);
    __syncthreads();
    if (tid < 64) {
        float s = b2[tid];
        const float* r = w2 + tid * 64;
        for (int i = 0; i < 64; i++) s += r[i] * h1[i];
        h2s[tid] = tanhf(s);
    }
    __syncthreads();

    float h2a = h2s[lid], h2b = h2s[lid + 32];
    float* tab = g_tables + tbi * TSTRIDE;
    int ebase = part * 256 + wid * 32;

    // W,U,G rows: 32 consecutive e per warp, coalesced over i
    for (int j = 0; j < 32; j++) {
        int e = ebase + j;
        const float* rw = w3 + e * 64;
        const float* ru = w3 + (1024 + e) * 64;
        const float* rg = w3 + (2048 + e) * 64;
        float sw = rw[lid] * h2a + rw[lid + 32] * h2b;
        float su = ru[lid] * h2a + ru[lid + 32] * h2b;
        float sg = rg[lid] * h2a + rg[lid + 32] * h2b;
        sw = warp_sum(sw); su = warp_sum(su); sg = warp_sum(sg);
        if (lid == 0) {
            sw += b3[e]; su += b3[1024 + e]; sg += b3[2048 + e];
            float u = su * (1.0f / (1.0f + expf(-sg))) * (1.0f / 128.0f);
            int k = e >> 3, d = e & 7;
            tab[k * 36 + 2 * d]          = sw;
            tab[k * 36 + 2 * d + 1]      = sw;
            tab[k * 36 + 16 + 2 * d]     = u;
            tab[k * 36 + 16 + 2 * d + 1] = u;
            Wsh[(e - part * 256)] = sw;
            Ush[(e - part * 256)] = u;
        }
    }

    // B rows: 32 rows for this part, 4 per warp
    #pragma unroll
    for (int j = 0; j < 4; j++) {
        int r = part * 32 + wid * 4 + j;
        const float* rr = w3 + (3072 + r) * 64;
        float s = rr[lid] * h2a + rr[lid + 32] * h2b;
        s = warp_sum(s);
        if (lid == 0) {
            s += b3[3072 + r];
            tab[r * 36 + 32] = s;
            tab[r * 36 + 33] = s;
        }
    }
    __syncthreads();

    // c' = W_k . U'_k for this part's 32 k
    if (tid < 32) {
        float c = 0.f;
        #pragma unroll
        for (int d = 0; d < 8; d++) c += Wsh[tid * 8 + d] * Ush[tid * 8 + d];
        int k = part * 32 + tid;
        tab[k * 36 + 34] = c;
        tab[k * 36 + 35] = c;
    }
}

// ---------------- phase 2: integrator ----------------
__device__ __forceinline__ void load_table(float* stab, int tbi)
{
    __syncthreads();   // previous RHS done reading stab
    const float4* src = (const float4*)(g_tables + tbi * TSTRIDE);
    float4* dst = (float4*)stab;
    #pragma unroll
    for (int i = 0; i < 9; i++)
        dst[threadIdx.x + i * 128] = src[threadIdx.x + i * 128];
    __syncthreads();
}

// Evaluate RHS for TWO packed pairs (4 points) sharing the same table row.
__device__ __forceinline__ void rhs_eval4(const float* stab,
                                          const ull* yA, const ull* yC,
                                          ull* dzA, ull* dzC,
                                          ull& ldzA, ull& ldzC)
{
    ull qA = 0ull, qC = 0ull;
    #pragma unroll
    for (int j = 0; j < 8; j++) { dzA[j] = 0ull; dzC[j] = 0ull; }

    #pragma unroll 2
    for (int k = 0; k < WIDTHK; k++) {
        const ulonglong2* row = (const ulonglong2*)(stab + k * 36);
        ulonglong2 w01 = row[0], w23 = row[1], w45 = row[2], w67 = row[3];
        ulonglong2 u01 = row[4], u23 = row[5], u45 = row[6], u67 = row[7];
        ulonglong2 bc  = row[8];              // (B,B | c',c')

        ull sA = ffma2(w01.x, yA[0], bc.x);
        sA = ffma2(w01.y, yA[1], sA);
        sA = ffma2(w23.x, yA[2], sA);
        sA = ffma2(w23.y, yA[3], sA);
        sA = ffma2(w45.x, yA[4], sA);
        sA = ffma2(w45.y, yA[5], sA);
        sA = ffma2(w67.x, yA[6], sA);
        sA = ffma2(w67.y, yA[7], sA);
        ull sC = ffma2(w01.x, yC[0], bc.x);
        sC = ffma2(w01.y, yC[1], sC);
        sC = ffma2(w23.x, yC[2], sC);
        sC = ffma2(w23.y, yC[3], sC);
        sC = ffma2(w45.x, yC[4], sC);
        sC = ffma2(w45.y, yC[5], sC);
        sC = ffma2(w67.x, yC[6], sC);
        sC = ffma2(w67.y, yC[7], sC);

        float fa, fb; upk2(sA, fa, fb);
        ull hA = pk2(tanha(fa), tanha(fb));
        float fc, fd; upk2(sC, fc, fd);
        ull hC = pk2(tanha(fc), tanha(fd));

        ull sqA = ffma2(hA, hA, (ull)NEGONE2);   // h^2 - 1
        qA = ffma2(bc.y, sqA, qA);               // q += c'*(h^2-1)
        ull sqC = ffma2(hC, hC, (ull)NEGONE2);
        qC = ffma2(bc.y, sqC, qC);

        dzA[0] = ffma2(hA, u01.x, dzA[0]); dzA[1] = ffma2(hA, u01.y, dzA[1]);
        dzA[2] = ffma2(hA, u23.x, dzA[2]); dzA[3] = ffma2(hA, u23.y, dzA[3]);
        dzA[4] = ffma2(hA, u45.x, dzA[4]); dzA[5] = ffma2(hA, u45.y, dzA[5]);
        dzA[6] = ffma2(hA, u67.x, dzA[6]); dzA[7] = ffma2(hA, u67.y, dzA[7]);
        dzC[0] = ffma2(hC, u01.x, dzC[0]); dzC[1] = ffma2(hC, u01.y, dzC[1]);
        dzC[2] = ffma2(hC, u23.x, dzC[2]); dzC[3] = ffma2(hC, u23.y, dzC[3]);
        dzC[4] = ffma2(hC, u45.x, dzC[4]); dzC[5] = ffma2(hC, u45.y, dzC[5]);
        dzC[6] = ffma2(hC, u67.x, dzC[6]); dzC[7] = ffma2(hC, u67.y, dzC[7]);
    }
    ldzA = qA;   // dlogp (scales folded into c')
    ldzC = qC;
}

__global__ void __launch_bounds__(128)
cnf_main(const float* __restrict__ ts, const float* __restrict__ z0,
         const float* __restrict__ lp0, float* __restrict__ out)
{
    __shared__ __align__(16) float stab[TSTRIDE];

    int p  = blockIdx.x * 128 + threadIdx.x;   // 0 .. 16383
    int pA = p, pB = p + QPTS, pC = p + 2 * QPTS, pD = p + 3 * QPTS;

    ull zA[8], yA[8], dzA[8], accA[8];
    ull zC[8], yC[8], dzC[8], accC[8];
    #pragma unroll
    for (int j = 0; j < 8; j++) {
        zA[j] = pk2(z0[pA * 8 + j], z0[pB * 8 + j]);
        zC[j] = pk2(z0[pC * 8 + j], z0[pD * 8 + j]);
    }
    ull lpA = pk2(lp0[pA], lp0[pB]);
    ull lpC = pk2(lp0[pC], lp0[pD]);

    const int ZT = TVALS * NPTS * DD;          // zt size in floats
    const ull two2 = pk2(2.0f, 2.0f);
    const ull C20  = pk2(20.0f/27.0f, 20.0f/27.0f);
    const ull C7   = pk2(7.0f/27.0f, 7.0f/27.0f);

    ull ldzA, ldzC, laccA, laccC;

    // store full state to slot s
#define STORE_STATE(s) do {                                                 \
        float a_, b_;                                                       \
        _Pragma("unroll")                                                   \
        for (int j = 0; j < 8; j++) {                                       \
            upk2(zA[j], a_, b_);                                            \
            out[((s) * NPTS + pA) * 8 + j] = a_;                            \
            out[((s) * NPTS + pB) * 8 + j] = b_;                            \
            upk2(zC[j], a_, b_);                                            \
            out[((s) * NPTS + pC) * 8 + j] = a_;                            \
            out[((s) * NPTS + pD) * 8 + j] = b_;                            \
        }                                                                   \
        upk2(lpA, a_, b_);                                                  \
        out[ZT + (s) * NPTS + pA] = a_; out[ZT + (s) * NPTS + pB] = b_;     \
        upk2(lpC, a_, b_);                                                  \
        out[ZT + (s) * NPTS + pC] = a_; out[ZT + (s) * NPTS + pD] = b_;     \
    } while (0)

    // Hermite partial: out[slot] = CZ*z + CHF*dz  (dz = current k1)
#define STORE_PART(s, CZ, CHF) do {                                         \
        float a_, b_; ull v_;                                               \
        _Pragma("unroll")                                                   \
        for (int j = 0; j < 8; j++) {                                       \
            v_ = ffma2(CHF, dzA[j], fmul2(CZ, zA[j])); upk2(v_, a_, b_);    \
            out[((s) * NPTS + pA) * 8 + j] = a_;                            \
            out[((s) * NPTS + pB) * 8 + j] = b_;                            \
            v_ = ffma2(CHF, dzC[j], fmul2(CZ, zC[j])); upk2(v_, a_, b_);    \
            out[((s) * NPTS + pC) * 8 + j] = a_;                            \
            out[((s) * NPTS + pD) * 8 + j] = b_;                            \
        }                                                                   \
        v_ = ffma2(CHF, ldzA, fmul2(CZ, lpA)); upk2(v_, a_, b_);            \
        out[ZT + (s) * NPTS + pA] = a_; out[ZT + (s) * NPTS + pB] = b_;     \
        v_ = ffma2(CHF, ldzC, fmul2(CZ, lpC)); upk2(v_, a_, b_);            \
        out[ZT + (s) * NPTS + pC] = a_; out[ZT + (s) * NPTS + pD] = b_;     \
    } while (0)

    // Hermite finalize: out[slot] += CZ*z + CHF*dz  (z = z1, dz = f1 = next k1)
#define FINAL_PART(s, CZ, CHF) do {                                         \
        float a_, b_; ull v_, ld_;                                          \
        _Pragma("unroll")                                                   \
        for (int j = 0; j < 8; j++) {                                       \
            ld_ = pk2(out[((s) * NPTS + pA) * 8 + j],                       \
                      out[((s) * NPTS + pB) * 8 + j]);                      \
            v_ = fadd2(ld_, ffma2(CHF, dzA[j], fmul2(CZ, zA[j])));          \
            upk2(v_, a_, b_);                                               \
            out[((s) * NPTS + pA) * 8 + j] = a_;                            \
            out[((s) * NPTS + pB) * 8 + j] = b_;                            \
            ld_ = pk2(out[((s) * NPTS + pC) * 8 + j],                       \
                      out[((s) * NPTS + pD) * 8 + j]);                      \
            v_ = fadd2(ld_, ffma2(CHF, dzC[j], fmul2(CZ, zC[j])));          \
            upk2(v_, a_, b_);                                               \
            out[((s) * NPTS + pC) * 8 + j] = a_;                            \
            out[((s) * NPTS + pD) * 8 + j] = b_;                            \
        }                                                                   \
        ld_ = pk2(out[ZT + (s) * NPTS + pA], out[ZT + (s) * NPTS + pB]);    \
        v_ = fadd2(ld_, ffma2(CHF, ldzA, fmul2(CZ, lpA)));                  \
        upk2(v_, a_, b_);                                                   \
        out[ZT + (s) * NPTS + pA] = a_; out[ZT + (s) * NPTS + pB] = b_;     \
        ld_ = pk2(out[ZT + (s) * NPTS + pC], out[ZT + (s) * NPTS + pD]);    \
        v_ = fadd2(ld_, ffma2(CHF, ldzC, fmul2(CZ, lpC)));                  \
        upk2(v_, a_, b_);                                                   \
        out[ZT + (s) * NPTS + pC] = a_; out[ZT + (s) * NPTS + pD] = b_;     \
    } while (0)

    // RK4 body after k1 is in dz; tables TMID, TEND; step size H
#define RK4_BODY(TMID, TEND, H) do {                                        \
        float hh_ = 0.5f * (H), h6_ = (H) / 6.0f;                           \
        ull hh2 = pk2(hh_, hh_), hf2 = pk2((H), (H)), h62 = pk2(h6_, h6_);  \
        _Pragma("unroll")                                                   \
        for (int j = 0; j < 8; j++) {                                       \
            accA[j] = dzA[j]; yA[j] = ffma2(hh2, dzA[j], zA[j]);            \
            accC[j] = dzC[j]; yC[j] = ffma2(hh2, dzC[j], zC[j]);            \
        }                                                                   \
        laccA = ldzA; laccC = ldzC;                                         \
        load_table(stab, TMID);                                             \
        rhs_eval4(stab, yA, yC, dzA, dzC, ldzA, ldzC);     /* k2 */         \
        _Pragma("unroll")                                                   \
        for (int j = 0; j < 8; j++) {                                       \
            accA[j] = ffma2(two2, dzA[j], accA[j]); yA[j] = ffma2(hh2, dzA[j], zA[j]); \
            accC[j] = ffma2(two2, dzC[j], accC[j]); yC[j] = ffma2(hh2, dzC[j], zC[j]); \
        }                                                                   \
        laccA = ffma2(two2, ldzA, laccA); laccC = ffma2(two2, ldzC, laccC); \
        rhs_eval4(stab, yA, yC, dzA, dzC, ldzA, ldzC);     /* k3 */         \
        _Pragma("unroll")                                                   \
        for (int j = 0; j < 8; j++) {                                       \
            accA[j] = ffma2(two2, dzA[j], accA[j]); yA[j] = ffma2(hf2, dzA[j], zA[j]); \
            accC[j] = ffma2(two2, dzC[j], accC[j]); yC[j] = ffma2(hf2, dzC[j], zC[j]); \
        }                                                                   \
        laccA = ffma2(two2, ldzA, laccA); laccC = ffma2(two2, ldzC, laccC); \
        load_table(stab, TEND);                                             \
        rhs_eval4(stab, yA, yC, dzA, dzC, ldzA, ldzC);     /* k4 */         \
        _Pragma("unroll")                                                   \
        for (int j = 0; j < 8; j++) {                                       \
            accA[j] = fadd2(accA[j], dzA[j]); zA[j] = ffma2(h62, accA[j], zA[j]); \
            accC[j] = fadd2(accC[j], dzC[j]); zC[j] = ffma2(h62, accC[j], zC[j]); \
        }                                                                   \
        laccA = fadd2(laccA, ldzA); lpA = ffma2(h62, laccA, lpA);           \
        laccC = fadd2(laccC, ldzC); lpC = ffma2(h62, laccC, lpC);           \
    } while (0)

    STORE_STATE(0);
    load_table(stab, 0);

    float h1 = ts[3] - ts[0];
    float h2 = ts[6] - ts[3];
    float h3 = ts[7] - ts[6];

    // ---- big step 0: [t0, t3], interiors t1 (th=1/3), t2 (th=2/3) ----
    rhs_eval4(stab, zA, zC, dzA, dzC, ldzA, ldzC);          // k1 @ t0
    {
        ull pa = pk2((4.0f/27.0f)*h1, (4.0f/27.0f)*h1);
        ull pb = pk2((2.0f/27.0f)*h1, (2.0f/27.0f)*h1);
        STORE_PART(1, C20, pa);     // H00(1/3)z0 + H10(1/3)h f0
        STORE_PART(2, C7,  pb);     // H00(2/3)z0 + H10(2/3)h f0
    }
    RK4_BODY(1, 2, h1);
    STORE_STATE(3);

    // ---- big step 1: [t3, t6], interiors t4, t5 ----
    rhs_eval4(stab, zA, zC, dzA, dzC, ldzA, ldzC);          // k1 @ t3 (f1 of step0)
    {
        ull fa = pk2(-(2.0f/27.0f)*h1, -(2.0f/27.0f)*h1);
        ull fb = pk2(-(4.0f/27.0f)*h1, -(4.0f/27.0f)*h1);
        FINAL_PART(1, C7,  fa);     // += H01(1/3)z1 + H11(1/3)h f1
        FINAL_PART(2, C20, fb);
        ull pa = pk2((4.0f/27.0f)*h2, (4.0f/27.0f)*h2);
        ull pb = pk2((2.0f/27.0f)*h2, (2.0f/27.0f)*h2);
        STORE_PART(4, C20, pa);
        STORE_PART(5, C7,  pb);
    }
    RK4_BODY(3, 4, h2);
    STORE_STATE(6);

    // ---- final step: [t6, t7] ----
    rhs_eval4(stab, zA, zC, dzA, dzC, ldzA, ldzC);          // k1 @ t6 (f1 of step1)
    {
        ull fa = pk2(-(2.0f/27.0f)*h2, -(2.0f/27.0f)*h2);
        ull fb = pk2(-(4.0f/27.0f)*h2, -(4.0f/27.0f)*h2);
        FINAL_PART(4, C7,  fa);
        FINAL_PART(5, C20, fb);
    }
    RK4_BODY(5, 6, h3);
    STORE_STATE(7);

#undef STORE_STATE
#undef STORE_PART
#undef FINAL_PART
#undef RK4_BODY
}

// ---------------- launch ----------------
extern "C" void kernel_launch(void* const* d_in, const int* in_sizes, int n_in,
                              void* d_out, int out_size)
{
    const float* ts  = (const float*)d_in[0];
    const float* z0  = (const float*)d_in[1];
    const float* lp0 = (const float*)d_in[2];
    const float* w1  = (const float*)d_in[3];
    const float* b1  = (const float*)d_in[4];
    const float* w2  = (const float*)d_in[5];
    const float* b2  = (const float*)d_in[6];
    const float* w3  = (const float*)d_in[7];
    const float* b3  = (const float*)d_in[8];
    float* out = (float*)d_out;

    hyper_kernel<<<NTAB * PARTS, 256>>>(ts, w1, b1, w2, b2, w3, b3);
    cnf_main<<<QPTS / 128, 128>>>(ts, z0, lp0, out);
}

// round 11
// speedup vs baseline: 1.4091x; 1.4091x over previous
#include <cuda_runtime.h>

typedef unsigned long long ull;

#define WIDTHK  128
#define DD      8
#define NPTS    65536
#define QPTS    (NPTS/4)      // 16384 threads, 4 points each
#define TVALS   8
#define TSTRIDE 4608          // floats per table: 128 rows * 36 floats
#define NTAB    9             // tables at ts[0..7] plus (ts[6]+ts[7])/2
#define PARTS   8             // hyper blocks per table

// ---------------- packed f32x2 helpers (sm_103a) ----------------
__device__ __forceinline__ ull pk2(float a, float b){ ull r; asm("mov.b64 %0,{%1,%2};":"=l"(r):"f"(a),"f"(b)); return r; }
__device__ __forceinline__ void upk2(ull v, float&a, float&b){ asm("mov.b64 {%0,%1},%2;":"=f"(a),"=f"(b):"l"(v)); }
__device__ __forceinline__ ull ffma2(ull a, ull b, ull c){ ull d; asm("fma.rn.f32x2 %0,%1,%2,%3;":"=l"(d):"l"(a),"l"(b),"l"(c)); return d; }
__device__ __forceinline__ ull fmul2(ull a, ull b){ ull d; asm("mul.rn.f32x2 %0,%1,%2;":"=l"(d):"l"(a),"l"(b)); return d; }
__device__ __forceinline__ ull fadd2(ull a, ull b){ ull d; asm("add.rn.f32x2 %0,%1,%2;":"=l"(d):"l"(a),"l"(b)); return d; }
__device__ __forceinline__ float tanha(float x){ float r; asm("tanh.approx.f32 %0,%1;":"=f"(r):"f"(x)); return r; }

#define NEGONE2 0xBF800000BF800000ULL   // (-1.f, -1.f)

// Hypernet tables. Per-k row (36 floats / 144B):
//  [0:16)  W[k][0..7] each duplicated  (8 x f32x2)
//  [16:32) U'[k][0..7] duplicated, U' = U*sigmoid(G)/128
//  [32:36) B,B,c',c'   where c' = W_k . U'_k
__device__ float g_tables[NTAB * TSTRIDE];

__device__ __forceinline__ float warp_sum(float v){
    #pragma unroll
    for (int o = 16; o > 0; o >>= 1)
        v += __shfl_xor_sync(0xffffffffu, v, o);
    return v;
}

// ---------------- phase 1: hypernetwork (coalesced, warp-per-row) ----------------
__global__ void __launch_bounds__(256)
hyper_kernel(const float* __restrict__ ts,
             const float* __restrict__ w1, const float* __restrict__ b1,
             const float* __restrict__ w2, const float* __restrict__ b2,
             const float* __restrict__ w3, const float* __restrict__ b3)
{
    __shared__ float h1[64], h2s[64];
    __shared__ float Wsh[128], Ush[128];   // this part's 16 k-rows x 8

    int blk  = blockIdx.x;
    int tbi  = blk / PARTS;
    int part = blk % PARTS;

    float t = (tbi < 8) ? ts[tbi] : 0.5f * (ts[6] + ts[7]);

    int tid = threadIdx.x;
    int lid = tid & 31, wid = tid >> 5;

    if (tid < 64) h1[tid] = tanhf(w1[tid] * t + b1[tid]);
    __syncthreads();
    if (tid < 64) {
        float s = b2[tid];
        const float* r = w2 + tid * 64;
        for (int i = 0; i < 64; i++) s += r[i] * h1[i];
        h2s[tid] = tanhf(s);
    }
    __syncthreads();

    float h2a = h2s[lid], h2b = h2s[lid + 32];
    float* tab = g_tables + tbi * TSTRIDE;
    int ebase = part * 128 + wid * 16;     // 8 warps x 16 e-rows = 128 rows/part

    // W,U,G rows: 16 consecutive e per warp, coalesced over i
    for (int j = 0; j < 16; j++) {
        int e = ebase + j;
        const float* rw = w3 + e * 64;
        const float* ru = w3 + (1024 + e) * 64;
        const float* rg = w3 + (2048 + e) * 64;
        float sw = rw[lid] * h2a + rw[lid + 32] * h2b;
        float su = ru[lid] * h2a + ru[lid + 32] * h2b;
        float sg = rg[lid] * h2a + rg[lid + 32] * h2b;
        sw = warp_sum(sw); su = warp_sum(su); sg = warp_sum(sg);
        if (lid == 0) {
            sw += b3[e]; su += b3[1024 + e]; sg += b3[2048 + e];
            float u = su * (1.0f / (1.0f + expf(-sg))) * (1.0f / 128.0f);
            int k = e >> 3, d = e & 7;
            tab[k * 36 + 2 * d]          = sw;
            tab[k * 36 + 2 * d + 1]      = sw;
            tab[k * 36 + 16 + 2 * d]     = u;
            tab[k * 36 + 16 + 2 * d + 1] = u;
            Wsh[(e - part * 128)] = sw;
            Ush[(e - part * 128)] = u;
        }
    }

    // B rows: 16 rows for this part, 2 per warp
    #pragma unroll
    for (int j = 0; j < 2; j++) {
        int r = part * 16 + wid * 2 + j;
        const float* rr = w3 + (3072 + r) * 64;
        float s = rr[lid] * h2a + rr[lid + 32] * h2b;
        s = warp_sum(s);
        if (lid == 0) {
            s += b3[3072 + r];
            tab[r * 36 + 32] = s;
            tab[r * 36 + 33] = s;
        }
    }
    __syncthreads();

    // c' = W_k . U'_k for this part's 16 k
    if (tid < 16) {
        float c = 0.f;
        #pragma unroll
        for (int d = 0; d < 8; d++) c += Wsh[tid * 8 + d] * Ush[tid * 8 + d];
        int k = part * 16 + tid;
        tab[k * 36 + 34] = c;
        tab[k * 36 + 35] = c;
    }
}

// ---------------- phase 2: integrator ----------------
__device__ __forceinline__ void load_table(float* stab, int tbi)
{
    __syncthreads();   // previous RHS done reading stab
    const float4* src = (const float4*)(g_tables + tbi * TSTRIDE);
    float4* dst = (float4*)stab;
    #pragma unroll
    for (int i = 0; i < 9; i++)
        dst[threadIdx.x + i * 128] = src[threadIdx.x + i * 128];
    __syncthreads();
}

// Evaluate RHS for TWO packed pairs (4 points) sharing the same table row.
__device__ __forceinline__ void rhs_eval4(const float* stab,
                                          const ull* yA, const ull* yC,
                                          ull* dzA, ull* dzC,
                                          ull& ldzA, ull& ldzC)
{
    ull qA = 0ull, qC = 0ull;
    #pragma unroll
    for (int j = 0; j < 8; j++) { dzA[j] = 0ull; dzC[j] = 0ull; }

    #pragma unroll 2
    for (int k = 0; k < WIDTHK; k++) {
        const ulonglong2* row = (const ulonglong2*)(stab + k * 36);
        ulonglong2 w01 = row[0], w23 = row[1], w45 = row[2], w67 = row[3];
        ulonglong2 u01 = row[4], u23 = row[5], u45 = row[6], u67 = row[7];
        ulonglong2 bc  = row[8];              // (B,B | c',c')

        ull sA = ffma2(w01.x, yA[0], bc.x);
        sA = ffma2(w01.y, yA[1], sA);
        sA = ffma2(w23.x, yA[2], sA);
        sA = ffma2(w23.y, yA[3], sA);
        sA = ffma2(w45.x, yA[4], sA);
        sA = ffma2(w45.y, yA[5], sA);
        sA = ffma2(w67.x, yA[6], sA);
        sA = ffma2(w67.y, yA[7], sA);
        ull sC = ffma2(w01.x, yC[0], bc.x);
        sC = ffma2(w01.y, yC[1], sC);
        sC = ffma2(w23.x, yC[2], sC);
        sC = ffma2(w23.y, yC[3], sC);
        sC = ffma2(w45.x, yC[4], sC);
        sC = ffma2(w45.y, yC[5], sC);
        sC = ffma2(w67.x, yC[6], sC);
        sC = ffma2(w67.y, yC[7], sC);

        float fa, fb; upk2(sA, fa, fb);
        ull hA = pk2(tanha(fa), tanha(fb));
        float fc, fd; upk2(sC, fc, fd);
        ull hC = pk2(tanha(fc), tanha(fd));

        ull sqA = ffma2(hA, hA, (ull)NEGONE2);   // h^2 - 1
        qA = ffma2(bc.y, sqA, qA);               // q += c'*(h^2-1)
        ull sqC = ffma2(hC, hC, (ull)NEGONE2);
        qC = ffma2(bc.y, sqC, qC);

        dzA[0] = ffma2(hA, u01.x, dzA[0]); dzA[1] = ffma2(hA, u01.y, dzA[1]);
        dzA[2] = ffma2(hA, u23.x, dzA[2]); dzA[3] = ffma2(hA, u23.y, dzA[3]);
        dzA[4] = ffma2(hA, u45.x, dzA[4]); dzA[5] = ffma2(hA, u45.y, dzA[5]);
        dzA[6] = ffma2(hA, u67.x, dzA[6]); dzA[7] = ffma2(hA, u67.y, dzA[7]);
        dzC[0] = ffma2(hC, u01.x, dzC[0]); dzC[1] = ffma2(hC, u01.y, dzC[1]);
        dzC[2] = ffma2(hC, u23.x, dzC[2]); dzC[3] = ffma2(hC, u23.y, dzC[3]);
        dzC[4] = ffma2(hC, u45.x, dzC[4]); dzC[5] = ffma2(hC, u45.y, dzC[5]);
        dzC[6] = ffma2(hC, u67.x, dzC[6]); dzC[7] = ffma2(hC, u67.y, dzC[7]);
    }
    ldzA = qA;   // dlogp (scales folded into c')
    ldzC = qC;
}

__global__ void __launch_bounds__(128)
cnf_main(const float* __restrict__ ts, const float* __restrict__ z0,
         const float* __restrict__ lp0, float* __restrict__ out)
{
    __shared__ __align__(16) float stab[TSTRIDE];

    int p  = blockIdx.x * 128 + threadIdx.x;   // 0 .. 16383
    int pA = p, pB = p + QPTS, pC = p + 2 * QPTS, pD = p + 3 * QPTS;

    ull zA[8], yA[8], dzA[8], accA[8], mA[8];
    ull zC[8], yC[8], dzC[8], accC[8], mC[8];
    #pragma unroll
    for (int j = 0; j < 8; j++) {
        zA[j] = pk2(z0[pA * 8 + j], z0[pB * 8 + j]);
        zC[j] = pk2(z0[pC * 8 + j], z0[pD * 8 + j]);
    }
    ull lpA = pk2(lp0[pA], lp0[pB]);
    ull lpC = pk2(lp0[pC], lp0[pD]);
    ull mlpA = 0ull, mlpC = 0ull;
    ull h8n2 = 0ull;                           // -(h_prev)/8 packed

    const int ZT = TVALS * NPTS * DD;          // zt size in floats
    const ull half2 = pk2(0.5f, 0.5f);
    const ull four2 = pk2(4.0f, 4.0f);

    // macro: store state vectors to slot s
#define STORE_STATE(s, ZV_A, ZV_C, LP_A, LP_C) do {                         \
        float a_, b_;                                                       \
        _Pragma("unroll")                                                   \
        for (int j = 0; j < 8; j++) {                                       \
            upk2(ZV_A[j], a_, b_);                                          \
            out[((s) * NPTS + pA) * 8 + j] = a_;                            \
            out[((s) * NPTS + pB) * 8 + j] = b_;                            \
            upk2(ZV_C[j], a_, b_);                                          \
            out[((s) * NPTS + pC) * 8 + j] = a_;                            \
            out[((s) * NPTS + pD) * 8 + j] = b_;                            \
        }                                                                   \
        upk2(LP_A, a_, b_);                                                 \
        out[ZT + (s) * NPTS + pA] = a_; out[ZT + (s) * NPTS + pB] = b_;     \
        upk2(LP_C, a_, b_);                                                 \
        out[ZT + (s) * NPTS + pC] = a_; out[ZT + (s) * NPTS + pD] = b_;     \
    } while (0)

    // slot 0 = initial state
    STORE_STATE(0, zA, zC, lpA, lpC);

    load_table(stab, 0);

    ull ldzA, ldzC, laccA, laccC;

    // ---- three big Kutta-RK3 steps over [ts[2i], ts[2i+2]] ----
    #pragma unroll 1
    for (int i = 0; i < 3; i++) {
        float h  = ts[2 * i + 2] - ts[2 * i];
        float hh = 0.5f * h, h8 = 0.125f * h, h6 = h / 6.0f;
        ull hh2 = pk2(hh, hh), h82 = pk2(h8, h8);
        ull h62 = pk2(h6, h6);
        ull twoh2 = pk2(2.0f * h, 2.0f * h), nh2 = pk2(-h, -h);

        // k1 = f(t_lo, z); table T[2i] resident
        rhs_eval4(stab, zA, zC, dzA, dzC, ldzA, ldzC);

        if (i > 0) {
            // finish previous step's Hermite midpoint (slot 2i-1):
            // z_mid = m + 0.5*z - (h_prev/8)*f2, f2 = this k1
            ull vA[8], vC[8];
            #pragma unroll
            for (int j = 0; j < 8; j++) {
                vA[j] = ffma2(h8n2, dzA[j], ffma2(half2, zA[j], mA[j]));
                vC[j] = ffma2(h8n2, dzC[j], ffma2(half2, zC[j], mC[j]));
            }
            ull vlA = ffma2(h8n2, ldzA, ffma2(half2, lpA, mlpA));
            ull vlC = ffma2(h8n2, ldzC, ffma2(half2, lpC, mlpC));
            STORE_STATE(2 * i - 1, vA, vC, vlA, vlC);
        }

        // m = 0.5*z + (h/8)*k1 for this step's midpoint
        #pragma unroll
        for (int j = 0; j < 8; j++) {
            mA[j] = ffma2(h82, dzA[j], fmul2(half2, zA[j]));
            mC[j] = ffma2(h82, dzC[j], fmul2(half2, zC[j]));
        }
        mlpA = ffma2(h82, ldzA, fmul2(half2, lpA));
        mlpC = ffma2(h82, ldzC, fmul2(half2, lpC));

        // acc = k1; y2 = z + (h/2) k1
        #pragma unroll
        for (int j = 0; j < 8; j++) {
            accA[j] = dzA[j]; yA[j] = ffma2(hh2, dzA[j], zA[j]);
            accC[j] = dzC[j]; yC[j] = ffma2(hh2, dzC[j], zC[j]);
        }
        laccA = ldzA; laccC = ldzC;

        load_table(stab, 2 * i + 1);           // midpoint table (= ts[2i+1])
        rhs_eval4(stab, yA, yC, dzA, dzC, ldzA, ldzC);     // k2
        // y3 = z - h*k1 + 2h*k2 ; acc += 4*k2
        #pragma unroll
        for (int j = 0; j < 8; j++) {
            yA[j] = ffma2(twoh2, dzA[j], ffma2(nh2, accA[j], zA[j]));
            accA[j] = ffma2(four2, dzA[j], accA[j]);
            yC[j] = ffma2(twoh2, dzC[j], ffma2(nh2, accC[j], zC[j]));
            accC[j] = ffma2(four2, dzC[j], accC[j]);
        }
        laccA = ffma2(four2, ldzA, laccA); laccC = ffma2(four2, ldzC, laccC);

        load_table(stab, 2 * i + 2);           // endpoint table (stays resident)
        rhs_eval4(stab, yA, yC, dzA, dzC, ldzA, ldzC);     // k3 @ t_end
        #pragma unroll
        for (int j = 0; j < 8; j++) {
            zA[j] = ffma2(h62, fadd2(accA[j], dzA[j]), zA[j]);
            zC[j] = ffma2(h62, fadd2(accC[j], dzC[j]), zC[j]);
        }
        lpA = ffma2(h62, fadd2(laccA, ldzA), lpA);
        lpC = ffma2(h62, fadd2(laccC, ldzC), lpC);

        STORE_STATE(2 * i + 2, zA, zC, lpA, lpC);

        h8n2 = pk2(-h8, -h8);
    }

    // ---- final small RK3 step over [ts[6], ts[7]]; table T6 resident ----
    {
        float h  = ts[7] - ts[6];
        float hh = 0.5f * h, h6 = h / 6.0f;
        ull hh2 = pk2(hh, hh), h62 = pk2(h6, h6);
        ull twoh2 = pk2(2.0f * h, 2.0f * h), nh2 = pk2(-h, -h);

        rhs_eval4(stab, zA, zC, dzA, dzC, ldzA, ldzC);     // k1 = f(t6, z6)

        // midpoint t5 of big step 2 (slot 5), f2 = this k1
        {
            ull vA[8], vC[8];
            #pragma unroll
            for (int j = 0; j < 8; j++) {
                vA[j] = ffma2(h8n2, dzA[j], ffma2(half2, zA[j], mA[j]));
                vC[j] = ffma2(h8n2, dzC[j], ffma2(half2, zC[j], mC[j]));
            }
            ull vlA = ffma2(h8n2, ldzA, ffma2(half2, lpA, mlpA));
            ull vlC = ffma2(h8n2, ldzC, ffma2(half2, lpC, mlpC));
            STORE_STATE(5, vA, vC, vlA, vlC);
        }

        #pragma unroll
        for (int j = 0; j < 8; j++) {
            accA[j] = dzA[j]; yA[j] = ffma2(hh2, dzA[j], zA[j]);
            accC[j] = dzC[j]; yC[j] = ffma2(hh2, dzC[j], zC[j]);
        }
        laccA = ldzA; laccC = ldzC;

        load_table(stab, 8);                   // t = (ts[6]+ts[7])/2
        rhs_eval4(stab, yA, yC, dzA, dzC, ldzA, ldzC);     // k2
        #pragma unroll
        for (int j = 0; j < 8; j++) {
            yA[j] = ffma2(twoh2, dzA[j], ffma2(nh2, accA[j], zA[j]));
            accA[j] = ffma2(four2, dzA[j], accA[j]);
            yC[j] = ffma2(twoh2, dzC[j], ffma2(nh2, accC[j], zC[j]));
            accC[j] = ffma2(four2, dzC[j], accC[j]);
        }
        laccA = ffma2(four2, ldzA, laccA); laccC = ffma2(four2, ldzC, laccC);

        load_table(stab, 7);                   // t = ts[7]
        rhs_eval4(stab, yA, yC, dzA, dzC, ldzA, ldzC);     // k3
        #pragma unroll
        for (int j = 0; j < 8; j++) {
            zA[j] = ffma2(h62, fadd2(accA[j], dzA[j]), zA[j]);
            zC[j] = ffma2(h62, fadd2(accC[j], dzC[j]), zC[j]);
        }
        lpA = ffma2(h62, fadd2(laccA, ldzA), lpA);
        lpC = ffma2(h62, fadd2(laccC, ldzC), lpC);

        STORE_STATE(7, zA, zC, lpA, lpC);
    }
#undef STORE_STATE
}

// ---------------- launch ----------------
extern "C" void kernel_launch(void* const* d_in, const int* in_sizes, int n_in,
                              void* d_out, int out_size)
{
    const float* ts  = (const float*)d_in[0];
    const float* z0  = (const float*)d_in[1];
    const float* lp0 = (const float*)d_in[2];
    const float* w1  = (const float*)d_in[3];
    const float* b1  = (const float*)d_in[4];
    const float* w2  = (const float*)d_in[5];
    const float* b2  = (const float*)d_in[6];
    const float* w3  = (const float*)d_in[7];
    const float* b3  = (const float*)d_in[8];
    float* out = (float*)d_out;

    hyper_kernel<<<NTAB * PARTS, 256>>>(ts, w1, b1, w2, b2, w3, b3);
    cnf_main<<<QPTS / 128, 128>>>(ts, z0, lp0, out);
}

// round 14
// speedup vs baseline: 1.8206x; 1.2920x over previous
#include <cuda_runtime.h>

typedef unsigned long long ull;

#define WIDTHK  128
#define DD      8
#define NPTS    65536
#define QPTS    (NPTS/4)      // 16384 threads, 4 points each
#define TVALS   8
#define TSTRIDE 4608          // floats per table: 128 rows * 36 floats
#define NTAB    9             // tables at ts[0..7] plus (ts[6]+ts[7])/2
#define PARTS   8             // hyper blocks per table

// ---------------- packed f32x2 helpers (sm_103a) ----------------
__device__ __forceinline__ ull pk2(float a, float b){ ull r; asm("mov.b64 %0,{%1,%2};":"=l"(r):"f"(a),"f"(b)); return r; }
__device__ __forceinline__ void upk2(ull v, float&a, float&b){ asm("mov.b64 {%0,%1},%2;":"=f"(a),"=f"(b):"l"(v)); }
__device__ __forceinline__ ull ffma2(ull a, ull b, ull c){ ull d; asm("fma.rn.f32x2 %0,%1,%2,%3;":"=l"(d):"l"(a),"l"(b),"l"(c)); return d; }
__device__ __forceinline__ ull fmul2(ull a, ull b){ ull d; asm("mul.rn.f32x2 %0,%1,%2;":"=l"(d):"l"(a),"l"(b)); return d; }
__device__ __forceinline__ ull fadd2(ull a, ull b){ ull d; asm("add.rn.f32x2 %0,%1,%2;":"=l"(d):"l"(a),"l"(b)); return d; }
__device__ __forceinline__ float tanha(float x){ float r; asm("tanh.approx.f32 %0,%1;":"=f"(r):"f"(x)); return r; }

#define NEGONE2 0xBF800000BF800000ULL   // (-1.f, -1.f)

// Hypernet tables. Per-k row (36 floats / 144B):
//  [0:16)  W[k][0..7] each duplicated  (8 x f32x2)
//  [16:32) U'[k][0..7] duplicated, U' = U*sigmoid(G)/128
//  [32:36) B,B,c',c'   where c' = W_k . U'_k
__device__ float g_tables[NTAB * TSTRIDE];

__device__ __forceinline__ float warp_sum(float v){
    #pragma unroll
    for (int o = 16; o > 0; o >>= 1)
        v += __shfl_xor_sync(0xffffffffu, v, o);
    return v;
}

// ---------------- phase 1: hypernetwork (coalesced, warp-per-row) ----------------
__global__ void __launch_bounds__(256)
hyper_kernel(const float* __restrict__ ts,
             const float* __restrict__ w1, const float* __restrict__ b1,
             const float* __restrict__ w2, const float* __restrict__ b2,
             const float* __restrict__ w3, const float* __restrict__ b3)
{
    __shared__ float h1[64], h2s[64];
    __shared__ float Wsh[128], Ush[128];   // this part's 16 k-rows x 8

    int blk  = blockIdx.x;
    int tbi  = blk / PARTS;
    int part = blk % PARTS;

    float t = (tbi < 8) ? ts[tbi] : 0.5f * (ts[6] + ts[7]);

    int tid = threadIdx.x;
    int lid = tid & 31, wid = tid >> 5;

    if (tid < 64) h1[tid] = tanhf(w1[tid] * t + b1[tid]);
    __syncthreads();
    if (tid < 64) {
        float s = b2[tid];
        const float* r = w2 + tid * 64;
        for (int i = 0; i < 64; i++) s += r[i] * h1[i];
        h2s[tid] = tanhf(s);
    }
    __syncthreads();

    float h2a = h2s[lid], h2b = h2s[lid + 32];
    float* tab = g_tables + tbi * TSTRIDE;
    int ebase = part * 128 + wid * 16;     // 8 warps x 16 e-rows = 128 rows/part

    // W,U,G rows: 16 consecutive e per warp, coalesced over i
    for (int j = 0; j < 16; j++) {
        int e = ebase + j;
        const float* rw = w3 + e * 64;
        const float* ru = w3 + (1024 + e) * 64;
        const float* rg = w3 + (2048 + e) * 64;
        float sw = rw[lid] * h2a + rw[lid + 32] * h2b;
        float su = ru[lid] * h2a + ru[lid + 32] * h2b;
        float sg = rg[lid] * h2a + rg[lid + 32] * h2b;
        sw = warp_sum(sw); su = warp_sum(su); sg = warp_sum(sg);
        if (lid == 0) {
            sw += b3[e]; su += b3[1024 + e]; sg += b3[2048 + e];
            float u = su * (1.0f / (1.0f + expf(-sg))) * (1.0f / 128.0f);
            int k = e >> 3, d = e & 7;
            tab[k * 36 + 2 * d]          = sw;
            tab[k * 36 + 2 * d + 1]      = sw;
            tab[k * 36 + 16 + 2 * d]     = u;
            tab[k * 36 + 16 + 2 * d + 1] = u;
            Wsh[(e - part * 128)] = sw;
            Ush[(e - part * 128)] = u;
        }
    }

    // B rows: 16 rows for this part, 2 per warp
    #pragma unroll
    for (int j = 0; j < 2; j++) {
        int r = part * 16 + wid * 2 + j;
        const float* rr = w3 + (3072 + r) * 64;
        float s = rr[lid] * h2a + rr[lid + 32] * h2b;
        s = warp_sum(s);
        if (lid == 0) {
            s += b3[3072 + r];
            tab[r * 36 + 32] = s;
            tab[r * 36 + 33] = s;
        }
    }
    __syncthreads();

    // c' = W_k . U'_k for this part's 16 k
    if (tid < 16) {
        float c = 0.f;
        #pragma unroll
        for (int d = 0; d < 8; d++) c += Wsh[tid * 8 + d] * Ush[tid * 8 + d];
        int k = part * 16 + tid;
        tab[k * 36 + 34] = c;
        tab[k * 36 + 35] = c;
    }
}

// ---------------- phase 2: integrator ----------------
__device__ __forceinline__ void load_table(float* stab, int tbi)
{
    __syncthreads();   // previous RHS done reading stab
    const float4* src = (const float4*)(g_tables + tbi * TSTRIDE);
    float4* dst = (float4*)stab;
    #pragma unroll
    for (int i = 0; i < 9; i++)
        dst[threadIdx.x + i * 128] = src[threadIdx.x + i * 128];
    __syncthreads();
}

// Evaluate RHS for TWO packed pairs (4 points) sharing the same table row.
__device__ __forceinline__ void rhs_eval4(const float* stab,
                                          const ull* yA, const ull* yC,
                                          ull* dzA, ull* dzC,
                                          ull& ldzA, ull& ldzC)
{
    ull qA = 0ull, qC = 0ull;
    #pragma unroll
    for (int j = 0; j < 8; j++) { dzA[j] = 0ull; dzC[j] = 0ull; }

    #pragma unroll 2
    for (int k = 0; k < WIDTHK; k++) {
        const ulonglong2* row = (const ulonglong2*)(stab + k * 36);
        ulonglong2 w01 = row[0], w23 = row[1], w45 = row[2], w67 = row[3];
        ulonglong2 u01 = row[4], u23 = row[5], u45 = row[6], u67 = row[7];
        ulonglong2 bc  = row[8];              // (B,B | c',c')

        ull sA = ffma2(w01.x, yA[0], bc.x);
        sA = ffma2(w01.y, yA[1], sA);
        sA = ffma2(w23.x, yA[2], sA);
        sA = ffma2(w23.y, yA[3], sA);
        sA = ffma2(w45.x, yA[4], sA);
        sA = ffma2(w45.y, yA[5], sA);
        sA = ffma2(w67.x, yA[6], sA);
        sA = ffma2(w67.y, yA[7], sA);
        ull sC = ffma2(w01.x, yC[0], bc.x);
        sC = ffma2(w01.y, yC[1], sC);
        sC = ffma2(w23.x, yC[2], sC);
        sC = ffma2(w23.y, yC[3], sC);
        sC = ffma2(w45.x, yC[4], sC);
        sC = ffma2(w45.y, yC[5], sC);
        sC = ffma2(w67.x, yC[6], sC);
        sC = ffma2(w67.y, yC[7], sC);

        float fa, fb; upk2(sA, fa, fb);
        ull hA = pk2(tanha(fa), tanha(fb));
        float fc, fd; upk2(sC, fc, fd);
        ull hC = pk2(tanha(fc), tanha(fd));

        ull sqA = ffma2(hA, hA, (ull)NEGONE2);   // h^2 - 1
        qA = ffma2(bc.y, sqA, qA);               // q += c'*(h^2-1)
        ull sqC = ffma2(hC, hC, (ull)NEGONE2);
        qC = ffma2(bc.y, sqC, qC);

        dzA[0] = ffma2(hA, u01.x, dzA[0]); dzA[1] = ffma2(hA, u01.y, dzA[1]);
        dzA[2] = ffma2(hA, u23.x, dzA[2]); dzA[3] = ffma2(hA, u23.y, dzA[3]);
        dzA[4] = ffma2(hA, u45.x, dzA[4]); dzA[5] = ffma2(hA, u45.y, dzA[5]);
        dzA[6] = ffma2(hA, u67.x, dzA[6]); dzA[7] = ffma2(hA, u67.y, dzA[7]);
        dzC[0] = ffma2(hC, u01.x, dzC[0]); dzC[1] = ffma2(hC, u01.y, dzC[1]);
        dzC[2] = ffma2(hC, u23.x, dzC[2]); dzC[3] = ffma2(hC, u23.y, dzC[3]);
        dzC[4] = ffma2(hC, u45.x, dzC[4]); dzC[5] = ffma2(hC, u45.y, dzC[5]);
        dzC[6] = ffma2(hC, u67.x, dzC[6]); dzC[7] = ffma2(hC, u67.y, dzC[7]);
    }
    ldzA = qA;   // dlogp (scales folded into c')
    ldzC = qC;
}

__global__ void __launch_bounds__(128)
cnf_main(const float* __restrict__ ts, const float* __restrict__ z0,
         const float* __restrict__ lp0, float* __restrict__ out)
{
    __shared__ __align__(16) float stab[TSTRIDE];

    int p  = blockIdx.x * 128 + threadIdx.x;   // 0 .. 16383
    int pA = p, pB = p + QPTS, pC = p + 2 * QPTS, pD = p + 3 * QPTS;

    ull zA[8], yA[8], dzA[8], mA[8];
    ull zC[8], yC[8], dzC[8], mC[8];
    #pragma unroll
    for (int j = 0; j < 8; j++) {
        zA[j] = pk2(z0[pA * 8 + j], z0[pB * 8 + j]);
        zC[j] = pk2(z0[pC * 8 + j], z0[pD * 8 + j]);
    }
    ull lpA = pk2(lp0[pA], lp0[pB]);
    ull lpC = pk2(lp0[pC], lp0[pD]);
    ull mlpA = 0ull, mlpC = 0ull;
    ull laccA = 0ull, laccC = 0ull;            // Simpson partial: g0 + 4*gmid
    ull h8n2 = 0ull;                           // -(h_prev)/8 packed
    ull h6p2 = 0ull;                           // (h_prev)/6 packed

    const int ZT = TVALS * NPTS * DD;          // zt size in floats
    const ull half2 = pk2(0.5f, 0.5f);
    const ull four2 = pk2(4.0f, 4.0f);

    // macro: store state vectors to slot s
#define STORE_STATE(s, ZV_A, ZV_C, LP_A, LP_C) do {                         \
        float a_, b_;                                                       \
        _Pragma("unroll")                                                   \
        for (int j = 0; j < 8; j++) {                                       \
            upk2(ZV_A[j], a_, b_);                                          \
            out[((s) * NPTS + pA) * 8 + j] = a_;                            \
            out[((s) * NPTS + pB) * 8 + j] = b_;                            \
            upk2(ZV_C[j], a_, b_);                                          \
            out[((s) * NPTS + pC) * 8 + j] = a_;                            \
            out[((s) * NPTS + pD) * 8 + j] = b_;                            \
        }                                                                   \
        upk2(LP_A, a_, b_);                                                 \
        out[ZT + (s) * NPTS + pA] = a_; out[ZT + (s) * NPTS + pB] = b_;     \
        upk2(LP_C, a_, b_);                                                 \
        out[ZT + (s) * NPTS + pC] = a_; out[ZT + (s) * NPTS + pD] = b_;     \
    } while (0)

    // slot 0 = initial state
    STORE_STATE(0, zA, zC, lpA, lpC);

    load_table(stab, 0);

    ull ldzA, ldzC;

    // ---- three big steps over [ts[2i], ts[2i+2]]:
    //      z via midpoint-RK2, lp via FSAL-Simpson (g0 + 4 gmid + g1)*h/6 ----
    #pragma unroll 1
    for (int i = 0; i < 3; i++) {
        float h  = ts[2 * i + 2] - ts[2 * i];
        float hh = 0.5f * h, h8 = 0.125f * h;
        ull hh2 = pk2(hh, hh), h82 = pk2(h8, h8), hf2 = pk2(h, h);

        // k1 = f(t_lo, z); table T[2i] resident. g0 (or g1 of prev step).
        rhs_eval4(stab, zA, zC, dzA, dzC, ldzA, ldzC);

        if (i > 0) {
            // finalize previous step's lp via Simpson with g1 = this ldz
            lpA = ffma2(h6p2, fadd2(laccA, ldzA), lpA);
            lpC = ffma2(h6p2, fadd2(laccC, ldzC), lpC);
            // store previous endpoint state (z already current, lp now final)
            STORE_STATE(2 * i, zA, zC, lpA, lpC);
            // previous step's Hermite midpoint (slot 2i-1):
            // v = m + 0.5*z - (h_prev/8)*f1
            ull vA[8], vC[8];
            #pragma unroll
            for (int j = 0; j < 8; j++) {
                vA[j] = ffma2(h8n2, dzA[j], ffma2(half2, zA[j], mA[j]));
                vC[j] = ffma2(h8n2, dzC[j], ffma2(half2, zC[j], mC[j]));
            }
            ull vlA = ffma2(h8n2, ldzA, ffma2(half2, lpA, mlpA));
            ull vlC = ffma2(h8n2, ldzC, ffma2(half2, lpC, mlpC));
            STORE_STATE(2 * i - 1, vA, vC, vlA, vlC);
        }

        // m = 0.5*z + (h/8)*k1 for this step's Hermite midpoint
        #pragma unroll
        for (int j = 0; j < 8; j++) {
            mA[j] = ffma2(h82, dzA[j], fmul2(half2, zA[j]));
            mC[j] = ffma2(h82, dzC[j], fmul2(half2, zC[j]));
        }
        mlpA = ffma2(h82, ldzA, fmul2(half2, lpA));
        mlpC = ffma2(h82, ldzC, fmul2(half2, lpC));

        // y = z + (h/2) k1 ; lacc = g0
        #pragma unroll
        for (int j = 0; j < 8; j++) {
            yA[j] = ffma2(hh2, dzA[j], zA[j]);
            yC[j] = ffma2(hh2, dzC[j], zC[j]);
        }
        laccA = ldzA; laccC = ldzC;

        load_table(stab, 2 * i + 1);           // midpoint table (= ts[2i+1])
        rhs_eval4(stab, yA, yC, dzA, dzC, ldzA, ldzC);     // k2, gmid
        // z += h * k2 ; lacc += 4*gmid
        #pragma unroll
        for (int j = 0; j < 8; j++) {
            zA[j] = ffma2(hf2, dzA[j], zA[j]);
            zC[j] = ffma2(hf2, dzC[j], zC[j]);
        }
        laccA = ffma2(four2, ldzA, laccA);
        laccC = ffma2(four2, ldzC, laccC);

        load_table(stab, 2 * i + 2);           // endpoint table for next k1
        h8n2 = pk2(-h8, -h8);
        h6p2 = pk2(h / 6.0f, h / 6.0f);
    }

    // ---- final small step over [ts[6], ts[7]]; table T6 resident ----
    {
        float h  = ts[7] - ts[6];
        float hh = 0.5f * h, h6 = h / 6.0f;
        ull hh2 = pk2(hh, hh), hf2 = pk2(h, h), h62 = pk2(h6, h6);

        rhs_eval4(stab, zA, zC, dzA, dzC, ldzA, ldzC);     // g @ t6 (= g1 of step2)

        // finalize step2 lp, store slot 6, Hermite slot 5
        lpA = ffma2(h6p2, fadd2(laccA, ldzA), lpA);
        lpC = ffma2(h6p2, fadd2(laccC, ldzC), lpC);
        STORE_STATE(6, zA, zC, lpA, lpC);
        {
            ull vA[8], vC[8];
            #pragma unroll
            for (int j = 0; j < 8; j++) {
                vA[j] = ffma2(h8n2, dzA[j], ffma2(half2, zA[j], mA[j]));
                vC[j] = ffma2(h8n2, dzC[j], ffma2(half2, zC[j], mC[j]));
            }
            ull vlA = ffma2(h8n2, ldzA, ffma2(half2, lpA, mlpA));
            ull vlC = ffma2(h8n2, ldzC, ffma2(half2, lpC, mlpC));
            STORE_STATE(5, vA, vC, vlA, vlC);
        }

        // y = z + (h/2) k1 ; lacc = g0
        #pragma unroll
        for (int j = 0; j < 8; j++) {
            yA[j] = ffma2(hh2, dzA[j], zA[j]);
            yC[j] = ffma2(hh2, dzC[j], zC[j]);
        }
        laccA = ldzA; laccC = ldzC;

        load_table(stab, 8);                   // t = (ts[6]+ts[7])/2
        rhs_eval4(stab, yA, yC, dzA, dzC, ldzA, ldzC);     // k2, gmid
        #pragma unroll
        for (int j = 0; j < 8; j++) {
            zA[j] = ffma2(hf2, dzA[j], zA[j]);
            zC[j] = ffma2(hf2, dzC[j], zC[j]);
        }
        laccA = ffma2(four2, ldzA, laccA);
        laccC = ffma2(four2, ldzC, laccC);

        load_table(stab, 7);                   // t = ts[7]
        rhs_eval4(stab, zA, zC, dzA, dzC, ldzA, ldzC);     // g1 @ (t7, z7)
        lpA = ffma2(h62, fadd2(laccA, ldzA), lpA);
        lpC = ffma2(h62, fadd2(laccC, ldzC), lpC);

        STORE_STATE(7, zA, zC, lpA, lpC);
    }
#undef STORE_STATE
}

// ---------------- launch ----------------
extern "C" void kernel_launch(void* const* d_in, const int* in_sizes, int n_in,
                              void* d_out, int out_size)
{
    const float* ts  = (const float*)d_in[0];
    const float* z0  = (const float*)d_in[1];
    const float* lp0 = (const float*)d_in[2];
    const float* w1  = (const float*)d_in[3];
    const float* b1  = (const float*)d_in[4];
    const float* w2  = (const float*)d_in[5];
    const float* b2  = (const float*)d_in[6];
    const float* w3  = (const float*)d_in[7];
    const float* b3  = (const float*)d_in[8];
    float* out = (float*)d_out;

    hyper_kernel<<<NTAB * PARTS, 256>>>(ts, w1, b1, w2, b2, w3, b3);
    cnf_main<<<QPTS / 128, 128>>>(ts, z0, lp0, out);
}

// round 17
// speedup vs baseline: 1.9021x; 1.0447x over previous
#include <cuda_runtime.h>

typedef unsigned long long ull;

#define WIDTHK  128
#define DD      8
#define NPTS    65536
#define QPTS    (NPTS/4)      // 16384 threads, 4 points each
#define TVALS   8
#define TSTRIDE 4608          // floats per table: 128 rows * 36 floats
#define NTAB    7             // t0, t1.5, t3, t4.5, t6, t6.5, t7
#define PARTS   8             // hyper blocks per table

// ---------------- packed f32x2 helpers (sm_103a) ----------------
__device__ __forceinline__ ull pk2(float a, float b){ ull r; asm("mov.b64 %0,{%1,%2};":"=l"(r):"f"(a),"f"(b)); return r; }
__device__ __forceinline__ void upk2(ull v, float&a, float&b){ asm("mov.b64 {%0,%1},%2;":"=f"(a),"=f"(b):"l"(v)); }
__device__ __forceinline__ ull ffma2(ull a, ull b, ull c){ ull d; asm("fma.rn.f32x2 %0,%1,%2,%3;":"=l"(d):"l"(a),"l"(b),"l"(c)); return d; }
__device__ __forceinline__ ull fmul2(ull a, ull b){ ull d; asm("mul.rn.f32x2 %0,%1,%2;":"=l"(d):"l"(a),"l"(b)); return d; }
__device__ __forceinline__ ull fadd2(ull a, ull b){ ull d; asm("add.rn.f32x2 %0,%1,%2;":"=l"(d):"l"(a),"l"(b)); return d; }
__device__ __forceinline__ float tanha(float x){ float r; asm("tanh.approx.f32 %0,%1;":"=f"(r):"f"(x)); return r; }

#define NEGONE2 0xBF800000BF800000ULL   // (-1.f, -1.f)

// Hypernet tables. Per-k row (36 floats / 144B):
//  [0:16)  W[k][0..7] each duplicated  (8 x f32x2)
//  [16:32) U'[k][0..7] duplicated, U' = U*sigmoid(G)/128
//  [32:36) B,B,c',c'   where c' = W_k . U'_k
__device__ float g_tables[NTAB * TSTRIDE];

__device__ __forceinline__ float warp_sum(float v){
    #pragma unroll
    for (int o = 16; o > 0; o >>= 1)
        v += __shfl_xor_sync(0xffffffffu, v, o);
    return v;
}

// ---------------- phase 1: hypernetwork (coalesced, warp-per-row) ----------------
__global__ void __launch_bounds__(256)
hyper_kernel(const float* __restrict__ ts,
             const float* __restrict__ w1, const float* __restrict__ b1,
             const float* __restrict__ w2, const float* __restrict__ b2,
             const float* __restrict__ w3, const float* __restrict__ b3)
{
    __shared__ float h1[64], h2s[64];
    __shared__ float Wsh[128], Ush[128];   // this part's 16 k-rows x 8

    int blk  = blockIdx.x;
    int tbi  = blk / PARTS;
    int part = blk % PARTS;

    float t;
    switch (tbi) {
        case 0: t = ts[0]; break;
        case 1: t = 0.5f * (ts[1] + ts[2]); break;   // midpoint of [t0,t3]
        case 2: t = ts[3]; break;
        case 3: t = 0.5f * (ts[4] + ts[5]); break;   // midpoint of [t3,t6]
        case 4: t = ts[6]; break;
        case 5: t = 0.5f * (ts[6] + ts[7]); break;
        default: t = ts[7]; break;
    }

    int tid = threadIdx.x;
    int lid = tid & 31, wid = tid >> 5;

    if (tid < 64) h1[tid] = tanhf(w1[tid] * t + b1[tid]);
    __syncthreads();
    if (tid < 64) {
        float s = b2[tid];
        const float* r = w2 + tid * 64;
        for (int i = 0; i < 64; i++) s += r[i] * h1[i];
        h2s[tid] = tanhf(s);
    }
    __syncthreads();

    float h2a = h2s[lid], h2b = h2s[lid + 32];
    float* tab = g_tables + tbi * TSTRIDE;
    int ebase = part * 128 + wid * 16;     // 8 warps x 16 e-rows = 128 rows/part

    // W,U,G rows: 16 consecutive e per warp, coalesced over i
    for (int j = 0; j < 16; j++) {
        int e = ebase + j;
        const float* rw = w3 + e * 64;
        const float* ru = w3 + (1024 + e) * 64;
        const float* rg = w3 + (2048 + e) * 64;
        float sw = rw[lid] * h2a + rw[lid + 32] * h2b;
        float su = ru[lid] * h2a + ru[lid + 32] * h2b;
        float sg = rg[lid] * h2a + rg[lid + 32] * h2b;
        sw = warp_sum(sw); su = warp_sum(su); sg = warp_sum(sg);
        if (lid == 0) {
            sw += b3[e]; su += b3[1024 + e]; sg += b3[2048 + e];
            float u = su * (1.0f / (1.0f + expf(-sg))) * (1.0f / 128.0f);
            int k = e >> 3, d = e & 7;
            tab[k * 36 + 2 * d]          = sw;
            tab[k * 36 + 2 * d + 1]      = sw;
            tab[k * 36 + 16 + 2 * d]     = u;
            tab[k * 36 + 16 + 2 * d + 1] = u;
            Wsh[(e - part * 128)] = sw;
            Ush[(e - part * 128)] = u;
        }
    }

    // B rows: 16 rows for this part, 2 per warp
    #pragma unroll
    for (int j = 0; j < 2; j++) {
        int r = part * 16 + wid * 2 + j;
        const float* rr = w3 + (3072 + r) * 64;
        float s = rr[lid] * h2a + rr[lid + 32] * h2b;
        s = warp_sum(s);
        if (lid == 0) {
            s += b3[3072 + r];
            tab[r * 36 + 32] = s;
            tab[r * 36 + 33] = s;
        }
    }
    __syncthreads();

    // c' = W_k . U'_k for this part's 16 k
    if (tid < 16) {
        float c = 0.f;
        #pragma unroll
        for (int d = 0; d < 8; d++) c += Wsh[tid * 8 + d] * Ush[tid * 8 + d];
        int k = part * 16 + tid;
        tab[k * 36 + 34] = c;
        tab[k * 36 + 35] = c;
    }
}

// ---------------- phase 2: integrator ----------------
__device__ __forceinline__ void load_table(float* stab, int tbi)
{
    __syncthreads();   // previous RHS done reading stab
    const float4* src = (const float4*)(g_tables + tbi * TSTRIDE);
    float4* dst = (float4*)stab;
    #pragma unroll
    for (int i = 0; i < 9; i++)
        dst[threadIdx.x + i * 128] = src[threadIdx.x + i * 128];
    __syncthreads();
}

// Evaluate RHS for TWO packed pairs (4 points) sharing the same table row.
__device__ __forceinline__ void rhs_eval4(const float* stab,
                                          const ull* yA, const ull* yC,
                                          ull* dzA, ull* dzC,
                                          ull& ldzA, ull& ldzC)
{
    ull qA = 0ull, qC = 0ull;
    #pragma unroll
    for (int j = 0; j < 8; j++) { dzA[j] = 0ull; dzC[j] = 0ull; }

    #pragma unroll 2
    for (int k = 0; k < WIDTHK; k++) {
        const ulonglong2* row = (const ulonglong2*)(stab + k * 36);
        ulonglong2 w01 = row[0], w23 = row[1], w45 = row[2], w67 = row[3];
        ulonglong2 u01 = row[4], u23 = row[5], u45 = row[6], u67 = row[7];
        ulonglong2 bc  = row[8];              // (B,B | c',c')

        ull sA = ffma2(w01.x, yA[0], bc.x);
        sA = ffma2(w01.y, yA[1], sA);
        sA = ffma2(w23.x, yA[2], sA);
        sA = ffma2(w23.y, yA[3], sA);
        sA = ffma2(w45.x, yA[4], sA);
        sA = ffma2(w45.y, yA[5], sA);
        sA = ffma2(w67.x, yA[6], sA);
        sA = ffma2(w67.y, yA[7], sA);
        ull sC = ffma2(w01.x, yC[0], bc.x);
        sC = ffma2(w01.y, yC[1], sC);
        sC = ffma2(w23.x, yC[2], sC);
        sC = ffma2(w23.y, yC[3], sC);
        sC = ffma2(w45.x, yC[4], sC);
        sC = ffma2(w45.y, yC[5], sC);
        sC = ffma2(w67.x, yC[6], sC);
        sC = ffma2(w67.y, yC[7], sC);

        float fa, fb; upk2(sA, fa, fb);
        ull hA = pk2(tanha(fa), tanha(fb));
        float fc, fd; upk2(sC, fc, fd);
        ull hC = pk2(tanha(fc), tanha(fd));

        ull sqA = ffma2(hA, hA, (ull)NEGONE2);   // h^2 - 1
        qA = ffma2(bc.y, sqA, qA);               // q += c'*(h^2-1)
        ull sqC = ffma2(hC, hC, (ull)NEGONE2);
        qC = ffma2(bc.y, sqC, qC);

        dzA[0] = ffma2(hA, u01.x, dzA[0]); dzA[1] = ffma2(hA, u01.y, dzA[1]);
        dzA[2] = ffma2(hA, u23.x, dzA[2]); dzA[3] = ffma2(hA, u23.y, dzA[3]);
        dzA[4] = ffma2(hA, u45.x, dzA[4]); dzA[5] = ffma2(hA, u45.y, dzA[5]);
        dzA[6] = ffma2(hA, u67.x, dzA[6]); dzA[7] = ffma2(hA, u67.y, dzA[7]);
        dzC[0] = ffma2(hC, u01.x, dzC[0]); dzC[1] = ffma2(hC, u01.y, dzC[1]);
        dzC[2] = ffma2(hC, u23.x, dzC[2]); dzC[3] = ffma2(hC, u23.y, dzC[3]);
        dzC[4] = ffma2(hC, u45.x, dzC[4]); dzC[5] = ffma2(hC, u45.y, dzC[5]);
        dzC[6] = ffma2(hC, u67.x, dzC[6]); dzC[7] = ffma2(hC, u67.y, dzC[7]);
    }
    ldzA = qA;   // dlogp (scales folded into c')
    ldzC = qC;
}

__global__ void __launch_bounds__(128)
cnf_main(const float* __restrict__ ts, const float* __restrict__ z0,
         const float* __restrict__ lp0, float* __restrict__ out)
{
    __shared__ __align__(16) float stab[TSTRIDE];

    int p  = blockIdx.x * 128 + threadIdx.x;   // 0 .. 16383
    int pA = p, pB = p + QPTS, pC = p + 2 * QPTS, pD = p + 3 * QPTS;

    ull zA[8], yA[8], dzA[8];
    ull zC[8], yC[8], dzC[8];
    ull m1A[8], m1C[8], m2A[8], m2C[8];        // Hermite partials for 2 interiors
    #pragma unroll
    for (int j = 0; j < 8; j++) {
        zA[j] = pk2(z0[pA * 8 + j], z0[pB * 8 + j]);
        zC[j] = pk2(z0[pC * 8 + j], z0[pD * 8 + j]);
    }
    ull lpA = pk2(lp0[pA], lp0[pB]);
    ull lpC = pk2(lp0[pC], lp0[pD]);
    ull mlp1A = 0ull, mlp1C = 0ull, mlp2A = 0ull, mlp2C = 0ull;
    ull laccA = 0ull, laccC = 0ull;            // Simpson partial: g0 + 4*gmid
    ull c2n = 0ull, c4n = 0ull, h6p2 = 0ull;   // prev-step: -(2/27)hp, -(4/27)hp, hp/6

    const int ZT = TVALS * NPTS * DD;          // zt size in floats
    const ull four2 = pk2(4.0f, 4.0f);
    const ull C20   = pk2(20.0f/27.0f, 20.0f/27.0f);
    const ull C7    = pk2( 7.0f/27.0f,  7.0f/27.0f);

    // macro: store state vectors to slot s
#define STORE_STATE(s, ZV_A, ZV_C, LP_A, LP_C) do {                         \
        float a_, b_;                                                       \
        _Pragma("unroll")                                                   \
        for (int j = 0; j < 8; j++) {                                       \
            upk2(ZV_A[j], a_, b_);                                          \
            out[((s) * NPTS + pA) * 8 + j] = a_;                            \
            out[((s) * NPTS + pB) * 8 + j] = b_;                            \
            upk2(ZV_C[j], a_, b_);                                          \
            out[((s) * NPTS + pC) * 8 + j] = a_;                            \
            out[((s) * NPTS + pD) * 8 + j] = b_;                            \
        }                                                                   \
        upk2(LP_A, a_, b_);                                                 \
        out[ZT + (s) * NPTS + pA] = a_; out[ZT + (s) * NPTS + pB] = b_;     \
        upk2(LP_C, a_, b_);                                                 \
        out[ZT + (s) * NPTS + pC] = a_; out[ZT + (s) * NPTS + pD] = b_;     \
    } while (0)

    // slot 0 = initial state
    STORE_STATE(0, zA, zC, lpA, lpC);

    load_table(stab, 0);

    ull ldzA, ldzC;

    // ---- two big steps over [ts[3i], ts[3i+3]]:
    //      z via midpoint-RK2; lp via FSAL-Simpson; interiors at theta=1/3,2/3
    //      via register-carried cubic Hermite partials ----
    #pragma unroll 1
    for (int i = 0; i < 2; i++) {
        float h  = ts[3 * i + 3] - ts[3 * i];
        float hh = 0.5f * h;
        ull hh2 = pk2(hh, hh), hf2 = pk2(h, h);
        ull c4h = pk2((4.0f/27.0f)*h, (4.0f/27.0f)*h);
        ull c2h = pk2((2.0f/27.0f)*h, (2.0f/27.0f)*h);

        // k1 = f(t_lo, z); table T[2i] resident. g0 (or g1 of prev step).
        rhs_eval4(stab, zA, zC, dzA, dzC, ldzA, ldzC);

        if (i > 0) {
            // finalize previous step's lp via Simpson with g1 = this ldz
            lpA = ffma2(h6p2, fadd2(laccA, ldzA), lpA);
            lpC = ffma2(h6p2, fadd2(laccC, ldzC), lpC);
            STORE_STATE(3 * i, zA, zC, lpA, lpC);
            // interiors: v1 = m1 + (7/27) z1 - (2/27) hp f1 (theta=1/3)
            //            v2 = m2 + (20/27) z1 - (4/27) hp f1 (theta=2/3)
            ull vA[8], vC[8];
            #pragma unroll
            for (int j = 0; j < 8; j++) {
                vA[j] = ffma2(c2n, dzA[j], ffma2(C7, zA[j], m1A[j]));
                vC[j] = ffma2(c2n, dzC[j], ffma2(C7, zC[j], m1C[j]));
            }
            ull vlA = ffma2(c2n, ldzA, ffma2(C7, lpA, mlp1A));
            ull vlC = ffma2(c2n, ldzC, ffma2(C7, lpC, mlp1C));
            STORE_STATE(3 * i - 2, vA, vC, vlA, vlC);
            #pragma unroll
            for (int j = 0; j < 8; j++) {
                vA[j] = ffma2(c4n, dzA[j], ffma2(C20, zA[j], m2A[j]));
                vC[j] = ffma2(c4n, dzC[j], ffma2(C20, zC[j], m2C[j]));
            }
            vlA = ffma2(c4n, ldzA, ffma2(C20, lpA, mlp2A));
            vlC = ffma2(c4n, ldzC, ffma2(C20, lpC, mlp2C));
            STORE_STATE(3 * i - 1, vA, vC, vlA, vlC);
        }

        // Hermite partials for this step:
        // m1 = (20/27) z + (4/27) h f0 ; m2 = (7/27) z + (2/27) h f0
        #pragma unroll
        for (int j = 0; j < 8; j++) {
            m1A[j] = ffma2(c4h, dzA[j], fmul2(C20, zA[j]));
            m1C[j] = ffma2(c4h, dzC[j], fmul2(C20, zC[j]));
            m2A[j] = ffma2(c2h, dzA[j], fmul2(C7, zA[j]));
            m2C[j] = ffma2(c2h, dzC[j], fmul2(C7, zC[j]));
        }
        mlp1A = ffma2(c4h, ldzA, fmul2(C20, lpA));
        mlp1C = ffma2(c4h, ldzC, fmul2(C20, lpC));
        mlp2A = ffma2(c2h, ldzA, fmul2(C7, lpA));
        mlp2C = ffma2(c2h, ldzC, fmul2(C7, lpC));

        // y = z + (h/2) k1 ; lacc = g0
        #pragma unroll
        for (int j = 0; j < 8; j++) {
            yA[j] = ffma2(hh2, dzA[j], zA[j]);
            yC[j] = ffma2(hh2, dzC[j], zC[j]);
        }
        laccA = ldzA; laccC = ldzC;

        load_table(stab, 2 * i + 1);           // midpoint table
        rhs_eval4(stab, yA, yC, dzA, dzC, ldzA, ldzC);     // k2, gmid
        // z += h * k2 ; lacc += 4*gmid
        #pragma unroll
        for (int j = 0; j < 8; j++) {
            zA[j] = ffma2(hf2, dzA[j], zA[j]);
            zC[j] = ffma2(hf2, dzC[j], zC[j]);
        }
        laccA = ffma2(four2, ldzA, laccA);
        laccC = ffma2(four2, ldzC, laccC);

        load_table(stab, 2 * i + 2);           // endpoint table for next k1
        c2n  = pk2(-(2.0f/27.0f)*h, -(2.0f/27.0f)*h);
        c4n  = pk2(-(4.0f/27.0f)*h, -(4.0f/27.0f)*h);
        h6p2 = pk2(h / 6.0f, h / 6.0f);
    }

    // ---- final small step over [ts[6], ts[7]]; table idx 4 (t6) resident ----
    {
        float h  = ts[7] - ts[6];
        float hh = 0.5f * h, h6 = h / 6.0f;
        ull hh2 = pk2(hh, hh), hf2 = pk2(h, h), h62 = pk2(h6, h6);

        rhs_eval4(stab, zA, zC, dzA, dzC, ldzA, ldzC);     // g @ t6 (= f1/g1 of big step 1)

        // finalize big-step-1 lp, store slot 6, interiors slots 4 & 5
        lpA = ffma2(h6p2, fadd2(laccA, ldzA), lpA);
        lpC = ffma2(h6p2, fadd2(laccC, ldzC), lpC);
        STORE_STATE(6, zA, zC, lpA, lpC);
        {
            ull vA[8], vC[8];
            #pragma unroll
            for (int j = 0; j < 8; j++) {
                vA[j] = ffma2(c2n, dzA[j], ffma2(C7, zA[j], m1A[j]));
                vC[j] = ffma2(c2n, dzC[j], ffma2(C7, zC[j], m1C[j]));
            }
            ull vlA = ffma2(c2n, ldzA, ffma2(C7, lpA, mlp1A));
            ull vlC = ffma2(c2n, ldzC, ffma2(C7, lpC, mlp1C));
            STORE_STATE(4, vA, vC, vlA, vlC);
            #pragma unroll
            for (int j = 0; j < 8; j++) {
                vA[j] = ffma2(c4n, dzA[j], ffma2(C20, zA[j], m2A[j]));
                vC[j] = ffma2(c4n, dzC[j], ffma2(C20, zC[j], m2C[j]));
            }
            vlA = ffma2(c4n, ldzA, ffma2(C20, lpA, mlp2A));
            vlC = ffma2(c4n, ldzC, ffma2(C20, lpC, mlp2C));
            STORE_STATE(5, vA, vC, vlA, vlC);
        }

        // y = z + (h/2) k1 ; lacc = g0
        #pragma unroll
        for (int j = 0; j < 8; j++) {
            yA[j] = ffma2(hh2, dzA[j], zA[j]);
            yC[j] = ffma2(hh2, dzC[j], zC[j]);
        }
        laccA = ldzA; laccC = ldzC;

        load_table(stab, 5);                   // t = (ts[6]+ts[7])/2
        rhs_eval4(stab, yA, yC, dzA, dzC, ldzA, ldzC);     // k2, gmid
        #pragma unroll
        for (int j = 0; j < 8; j++) {
            zA[j] = ffma2(hf2, dzA[j], zA[j]);
            zC[j] = ffma2(hf2, dzC[j], zC[j]);
        }
        laccA = ffma2(four2, ldzA, laccA);
        laccC = ffma2(four2, ldzC, laccC);

        load_table(stab, 6);                   // t = ts[7]
        rhs_eval4(stab, zA, zC, dzA, dzC, ldzA, ldzC);     // g1 @ (t7, z7)
        lpA = ffma2(h62, fadd2(laccA, ldzA), lpA);
        lpC = ffma2(h62, fadd2(laccC, ldzC), lpC);

        STORE_STATE(7, zA, zC, lpA, lpC);
    }
#undef STORE_STATE
}

// ---------------- launch ----------------
extern "C" void kernel_launch(void* const* d_in, const int* in_sizes, int n_in,
                              void* d_out, int out_size)
{
    const float* ts  = (const float*)d_in[0];
    const float* z0  = (const float*)d_in[1];
    const float* lp0 = (const float*)d_in[2];
    const float* w1  = (const float*)d_in[3];
    const float* b1  = (const float*)d_in[4];
    const float* w2  = (const float*)d_in[5];
    const float* b2  = (const float*)d_in[6];
    const float* w3  = (const float*)d_in[7];
    const float* b3  = (const float*)d_in[8];
    float* out = (float*)d_out;

    hyper_kernel<<<NTAB * PARTS, 256>>>(ts, w1, b1, w2, b2, w3, b3);
    cnf_main<<<QPTS / 128, 128>>>(ts, z0, lp0, out);
}